// round 16
// baseline (speedup 1.0000x reference)
#include <cuda_runtime.h>
#include <cuda_fp16.h>
#include <cstdint>

#define NN 100000
#define EE 1000000
#define HH 128
#define FN 64
#define FE 32
#define CN 12
#define CE 4
#define NT_EDGE ((EE + 127) / 128)   // 7813
#define EPAD (NT_EDGE * 128)         // 1000064
#define GRID_P 148
#define NBLK ((NN + 255) / 256)      // 391

// ---------------------------------------------------------------------------
// Scratch (device globals — no cudaMalloc allowed)
// ---------------------------------------------------------------------------
__device__ float g_xw [(size_t)NN * HH];
__device__ float g_dinv[NN];
__device__ int   g_deg [NN];
__device__ int   g_part[NN];
__device__ int   g_rs  [NN];
__device__ int   g_cur [NN];
__device__ int   g_blksum[NBLK + 1];
__device__ int   g_blkoff[NBLK + 1];
__device__ int   g_csrc[EPAD];
__device__ int   g_ceid[EPAD];
__device__ int   g_ctgt[EPAD];
__device__ unsigned char g_segs[EPAD];
__device__ int   g_utgt[EPAD];
__device__ int   g_nseg[NT_EDGE];

__device__ __align__(16) __half g_xh [(size_t)NN * FN];
__device__ __align__(16) __half g_xl [(size_t)NN * FN];
__device__ __align__(16) __half g_hh [(size_t)NN * HH];
__device__ __align__(16) __half g_hl [(size_t)NN * HH];
__device__ __align__(16) __half g_Q  [(size_t)NN * HH];
__device__ __align__(16) __half g_ea16[(size_t)EE * FE];
__device__ __align__(16) __half g_eap[(size_t)EPAD * FE];
__device__ __align__(16) __half g_w1a16[128 * 128];
__device__ __align__(16) __half g_w1c16[128 * 32];

// node-path weight transposes (hi/lo), N padded to 128 rows
__device__ __align__(16) __half g_wWe_h[128 * 64],  g_wWe_l[128 * 64];
__device__ __align__(16) __half g_wC1_h[128 * 128], g_wC1_l[128 * 128];
__device__ __align__(16) __half g_wC2_h[128 * 128], g_wC2_l[128 * 128];
__device__ __align__(16) __half g_wN1_h[128 * 128], g_wN1_l[128 * 128];
__device__ __align__(16) __half g_w1b_h[128 * 128], g_w1b_l[128 * 128];

// ---------------------------------------------------------------------------
// Degree / normalization / CSR build
// ---------------------------------------------------------------------------
__global__ void k_deg_init(int* __restrict__ deg) {
    int i = blockIdx.x * blockDim.x + threadIdx.x;
    if (i < NN) deg[i] = 0;
}
__global__ void k_deg_edges(const int* __restrict__ col, int* __restrict__ deg) {
    int e = blockIdx.x * blockDim.x + threadIdx.x;
    if (e < EE) atomicAdd(&deg[col[e]], 1);
}
__global__ void k_dinv(const int* __restrict__ deg, float* __restrict__ dinv) {
    int i = blockIdx.x * blockDim.x + threadIdx.x;
    if (i < NN) dinv[i] = rsqrtf((float)(deg[i] + 1));
}
__global__ void k_scan1(const int* __restrict__ deg, int* __restrict__ part,
                        int* __restrict__ blksum)
{
    __shared__ int s[256];
    int tid = threadIdx.x;
    int i = blockIdx.x * 256 + tid;
    int v = (i < NN) ? deg[i] : 0;
    s[tid] = v;
    __syncthreads();
#pragma unroll
    for (int off = 1; off < 256; off <<= 1) {
        int x = (tid >= off) ? s[tid - off] : 0;
        __syncthreads();
        s[tid] += x;
        __syncthreads();
    }
    if (i < NN) part[i] = s[tid] - v;
    if (tid == 255) blksum[blockIdx.x] = s[255];
}
__global__ void k_scan2(const int* __restrict__ blksum, int* __restrict__ blkoff)
{
    if (threadIdx.x == 0) {
        int acc = 0;
        for (int b = 0; b < NBLK; b++) { blkoff[b] = acc; acc += blksum[b]; }
    }
}
__global__ void k_scan3(const int* __restrict__ part, const int* __restrict__ blkoff,
                        int* __restrict__ rs, int* __restrict__ cur)
{
    int i = blockIdx.x * blockDim.x + threadIdx.x;
    if (i < NN) {
        int v = part[i] + blkoff[i >> 8];
        rs[i] = v;
        cur[i] = v;
    }
}
__global__ void k_fill(const int* __restrict__ row, const int* __restrict__ col,
                       int* __restrict__ cur, int* __restrict__ csrc,
                       int* __restrict__ ceid, int* __restrict__ ctgt)
{
    int e = blockIdx.x * blockDim.x + threadIdx.x;
    if (e < EE) {
        int t = col[e];
        int pos = atomicAdd(&cur[t], 1);
        csrc[pos] = row[e];
        ceid[pos] = e;
        ctgt[pos] = t;
    }
}
__global__ void k_pad(int* __restrict__ csrc, int* __restrict__ ceid,
                      int* __restrict__ ctgt)
{
    int i = EE + blockIdx.x * blockDim.x + threadIdx.x;
    if (i < EPAD) {
        csrc[i] = csrc[EE - 1];
        ceid[i] = ceid[EE - 1];
        ctgt[i] = ctgt[EE - 1];
    }
}
// per-tile segment metadata: warp per tile
__global__ void k_meta(const int* __restrict__ ctgt, unsigned char* __restrict__ segs,
                       int* __restrict__ utgt, int* __restrict__ nseg)
{
    int tile = (blockIdx.x * blockDim.x + threadIdx.x) >> 5;
    int lane = threadIdx.x & 31;
    if (tile >= NT_EDGE) return;
    int p0 = tile * 128;
    int ns = 0;
    for (int c = 0; c < 4; c++) {
        int i = c * 32 + lane;
        int p = p0 + i;
        int t = ctgt[p];
        int b = (i == 0) ? 1 : (t != ctgt[p - 1]);
        unsigned mask = __ballot_sync(0xffffffffu, b);
        int incl = __popc(mask & (0xffffffffu >> (31 - lane)));
        int seg = ns + incl - 1;
        segs[p] = (unsigned char)seg;
        if (b) utgt[p0 + seg] = t;
        ns += __popc(mask);
    }
    if (lane == 0) nseg[tile] = ns;
}
// permute ea into CSR order: 4 threads per entry (16B each)
__global__ void k_permea(const int* __restrict__ ceid, const __half* __restrict__ ea16,
                         __half* __restrict__ eap)
{
    size_t i = (size_t)blockIdx.x * blockDim.x + threadIdx.x;
    if (i >= (size_t)EPAD * 4) return;
    size_t p = i >> 2;
    int sub = (int)(i & 3);
    int e = ceid[p];
    *(uint4*)&eap[p * FE + sub * 8] =
        *(const uint4*)&ea16[(size_t)e * FE + sub * 8];
}

// ---------------------------------------------------------------------------
// splits / conversions
// ---------------------------------------------------------------------------
__global__ void k_splitA(const float* __restrict__ in, __half* __restrict__ hi,
                         __half* __restrict__ lo, size_t n)
{
    size_t i = (size_t)blockIdx.x * blockDim.x + threadIdx.x;
    if (i < n) {
        float x = in[i];
        __half h = __float2half_rn(x);
        hi[i] = h;
        lo[i] = __float2half_rn(x - __half2float(h));
    }
}
__global__ void k_splitWt(const float* __restrict__ W, __half* __restrict__ hi,
                          __half* __restrict__ lo, int K, int Nn)
{
    int i = blockIdx.x * blockDim.x + threadIdx.x;
    if (i < 128 * K) {
        int n = i / K, k = i % K;
        float x = (n < Nn) ? W[(size_t)k * Nn + n] : 0.f;
        __half h = __float2half_rn(x);
        hi[i] = h;
        lo[i] = __float2half_rn(x - __half2float(h));
    }
}
__global__ void k_tof16_v(const float4* __restrict__ in, uint4* __restrict__ o, size_t n8)
{
    size_t i = (size_t)blockIdx.x * blockDim.x + threadIdx.x;
    if (i >= n8) return;
    float4 a = in[i * 2];
    float4 b = in[i * 2 + 1];
    __half2 h[4];
    h[0] = __floats2half2_rn(a.x, a.y);
    h[1] = __floats2half2_rn(a.z, a.w);
    h[2] = __floats2half2_rn(b.x, b.y);
    h[3] = __floats2half2_rn(b.z, b.w);
    o[i] = *reinterpret_cast<const uint4*>(h);
}
// W1 rows 0..127 -> W1a^T [128n][128k] fp16
__global__ void k_w1a16(const float* __restrict__ W1, __half* __restrict__ o)
{
    int i = blockIdx.x * blockDim.x + threadIdx.x;
    if (i < 128 * 128) {
        int n = i >> 7, k = i & 127;
        o[i] = __float2half_rn(W1[(size_t)k * 128 + n]);
    }
}
// W1 rows 256..287 -> W1c^T [128n][32k] fp16
__global__ void k_w1c16(const float* __restrict__ W1, __half* __restrict__ o)
{
    int i = blockIdx.x * blockDim.x + threadIdx.x;
    if (i < 128 * 32) {
        int n = i >> 5, k = i & 31;
        o[i] = __float2half_rn(W1[(size_t)(256 + k) * 128 + n]);
    }
}

// ---------------------------------------------------------------------------
// CSR pull aggregation: warp per node.
// ---------------------------------------------------------------------------
__global__ __launch_bounds__(256)
void k_pull(const float* __restrict__ xw, const int* __restrict__ csr,
            const int* __restrict__ rs, const int* __restrict__ deg,
            const float* __restrict__ dinv, const float* __restrict__ bias,
            __half* __restrict__ hh, __half* __restrict__ hl)
{
    int wid = (blockIdx.x * 256 + threadIdx.x) >> 5;
    int lane = threadIdx.x & 31;
    if (wid >= NN) return;
    int t = wid;
    float dt = dinv[t];
    float d2 = dt * dt;
    const float4* xw4 = (const float4*)xw;
    float4 a = xw4[(size_t)t * 32 + lane];
    float4 acc;
    acc.x = a.x * d2; acc.y = a.y * d2; acc.z = a.z * d2; acc.w = a.w * d2;

    int start = rs[t];
    int n = deg[t];
    for (int i = 0; i < n; i++) {
        int s = __ldg(&csr[start + i]);
        float c = dinv[s] * dt;
        float4 v = xw4[(size_t)s * 32 + lane];
        acc.x += v.x * c; acc.y += v.y * c; acc.z += v.z * c; acc.w += v.w * c;
    }

    float4 b = *(const float4*)&bias[lane * 4];
    float h0 = fmaxf(acc.x + b.x, 0.f);
    float h1 = fmaxf(acc.y + b.y, 0.f);
    float h2 = fmaxf(acc.z + b.z, 0.f);
    float h3 = fmaxf(acc.w + b.w, 0.f);

    __half2 hi[2], lo[2];
    hi[0] = __floats2half2_rn(h0, h1);
    hi[1] = __floats2half2_rn(h2, h3);
    float l0 = h0 - __half2float(__low2half(hi[0]));
    float l1 = h1 - __half2float(__high2half(hi[0]));
    float l2 = h2 - __half2float(__low2half(hi[1]));
    float l3 = h3 - __half2float(__high2half(hi[1]));
    lo[0] = __floats2half2_rn(l0, l1);
    lo[1] = __floats2half2_rn(l2, l3);
    *(uint2*)&hh[(size_t)t * HH + lane * 4] = *reinterpret_cast<const uint2*>(hi);
    *(uint2*)&hl[(size_t)t * HH + lane * 4] = *reinterpret_cast<const uint2*>(lo);
}

// ---------------------------------------------------------------------------
// mma helpers
// ---------------------------------------------------------------------------
__device__ __forceinline__ uint32_t sw128(uint32_t byte_off) {
    return byte_off ^ ((byte_off >> 3) & 0x70);
}
__device__ __forceinline__ void ldsm_x4(uint32_t (&r)[4], uint32_t addr) {
    asm volatile("ldmatrix.sync.aligned.m8n8.x4.shared.b16 {%0,%1,%2,%3}, [%4];"
                 : "=r"(r[0]), "=r"(r[1]), "=r"(r[2]), "=r"(r[3]) : "r"(addr));
}
__device__ __forceinline__ void mma_f16(float (&d)[4], const uint32_t (&a)[4],
                                        uint32_t b0, uint32_t b1) {
    asm volatile("mma.sync.aligned.m16n8k16.row.col.f32.f16.f16.f32 "
                 "{%0,%1,%2,%3},{%4,%5,%6,%7},{%8,%9},{%0,%1,%2,%3};"
                 : "+f"(d[0]), "+f"(d[1]), "+f"(d[2]), "+f"(d[3])
                 : "r"(a[0]), "r"(a[1]), "r"(a[2]), "r"(a[3]), "r"(b0), "r"(b1));
}
__device__ __forceinline__ void cp16(uint32_t saddr, const void* gaddr) {
    asm volatile("cp.async.cg.shared.global [%0], [%1], 16;" :: "r"(saddr), "l"(gaddr));
}
__device__ __forceinline__ void bulk_ld(uint32_t dst, const void* src, uint32_t bytes,
                                        uint32_t mbar) {
    asm volatile("cp.async.bulk.shared::cluster.global.mbarrier::complete_tx::bytes "
                 "[%0], [%1], %2, [%3];"
                 :: "r"(dst), "l"(src), "r"(bytes), "r"(mbar) : "memory");
}
__device__ __forceinline__ void mbar_init(uint32_t mbar, uint32_t cnt) {
    asm volatile("mbarrier.init.shared.b64 [%0], %1;" :: "r"(mbar), "r"(cnt) : "memory");
}
__device__ __forceinline__ void mbar_expect(uint32_t mbar, uint32_t bytes) {
    asm volatile("mbarrier.arrive.expect_tx.shared.b64 _, [%0], %1;"
                 :: "r"(mbar), "r"(bytes) : "memory");
}
__device__ __forceinline__ void mbar_wait(uint32_t mbar, uint32_t parity) {
    uint32_t done = 0;
    while (!done) {
        asm volatile("{\n\t.reg .pred p;\n\t"
                     "mbarrier.try_wait.parity.shared::cta.b64 p, [%1], %2;\n\t"
                     "selp.b32 %0, 1, 0, p;\n\t}"
                     : "=r"(done) : "r"(mbar), "r"(parity) : "memory");
    }
}

// ---------------------------------------------------------------------------
// Unified node-path GEMM: persistent, split-fp16 3-pass.
// EPI: 0=relu+split  1=plain fp32  4=fp16 out  5=fused node head
// ---------------------------------------------------------------------------
#define MM_SM_B   0
#define MM_SM_A   65536
#define MM_SM_BIAS (65536 + 3 * 32768)
#define MM_SM_TS  (MM_SM_BIAS + 512)
#define MM_SM_W2  (MM_SM_TS + 33280)
#define MM_SM_B2  (MM_SM_W2 + 3072)
#define MM_SM_END (MM_SM_B2 + 64)

template<int KCH, int EPI>
__global__ __launch_bounds__(512, 1)
void k_mm(const __half* __restrict__ Ah, const __half* __restrict__ Al,
          const __half* __restrict__ Bth, const __half* __restrict__ Btl,
          const float* __restrict__ bias,
          float* __restrict__ outF,
          __half* __restrict__ outH, __half* __restrict__ outL,
          const float* __restrict__ W2h, const float* __restrict__ b2h,
          int M, int Nn)
{
    constexpr int K = KCH * 64;
    extern __shared__ char sm[];
    uint32_t smb = (uint32_t)__cvta_generic_to_shared(sm);
    float* b1s = (float*)(sm + MM_SM_BIAS);
    float* tS  = (float*)(sm + MM_SM_TS);
    float* w2s = (float*)(sm + MM_SM_W2);
    float* b2s = (float*)(sm + MM_SM_B2);

    const int tid  = threadIdx.x;
    const int lane = tid & 31;
    const int w    = tid >> 5;
    const int wm   = w & 3, wn = w >> 2;
    const int m0   = wm * 32, n0 = wn * 32;

    const int NT = (M + 127) / 128;
    int nLocal = 0;
    for (int t = blockIdx.x; t < NT; t += GRID_P) nLocal++;
    if (nLocal == 0) return;
    const int totalQ = nLocal * KCH;

    for (int idx = tid; idx < 2 * KCH * 1024; idx += 512) {
        int b = idx >> 10, rem = idx & 1023;
        int n = rem >> 3, fc = rem & 7;
        int cb = b >> 1, hl = b & 1;
        const __half* src = (hl ? Btl : Bth) + (size_t)n * K + cb * 64 + fc * 8;
        cp16(smb + MM_SM_B + b * 16384 + sw128((uint32_t)(n * 128 + fc * 16)), src);
    }
    asm volatile("cp.async.commit_group;");

    if (tid < 128) b1s[tid] = (bias && tid < Nn) ? bias[tid] : 0.f;
    if (EPI == 5) {
        for (int i = tid; i < 64 * CN; i += 512) w2s[i] = W2h[i];
        if (tid < CN) b2s[tid] = b2h[tid];
    }
    __syncthreads();

    auto fill = [&](int q) {
        int k = q / KCH, c = q - k * KCH;
        int m0g = (blockIdx.x + k * GRID_P) * 128;
        uint32_t abase = smb + MM_SM_A + (q % 3) * 32768;
#pragma unroll
        for (int it = 0; it < 2; it++) {
            int idx = tid + it * 512;
            int fr = idx >> 3, fc = idx & 7;
            int gm = min(m0g + fr, M - 1);
            size_t so = (size_t)gm * K + c * 64 + fc * 8;
            uint32_t d = sw128((uint32_t)(fr * 128 + fc * 16));
            cp16(abase + d, Ah + so);
            cp16(abase + 16384 + d, Al + so);
        }
        asm volatile("cp.async.commit_group;");
    };

    fill(0);
    if (totalQ > 1) fill(1);

    const int gi   = lane & 7;
    const int gA_r = (lane >> 3) & 1;
    const int gA_c = lane >> 4;
    const int gB_r = lane >> 4;
    const int gB_c = (lane >> 3) & 1;

    float acc[2][4][4];

    for (int q = 0; q < totalQ; q++) {
        int k = q / KCH, c = q - k * KCH;

        if (q + 1 < totalQ) { asm volatile("cp.async.wait_group 1;" ::: "memory"); }
        else                { asm volatile("cp.async.wait_group 0;" ::: "memory"); }
        __syncthreads();
        if (q + 2 < totalQ) fill(q + 2);

        if (c == 0) {
#pragma unroll
            for (int i = 0; i < 2; i++)
#pragma unroll
                for (int j = 0; j < 4; j++)
#pragma unroll
                    for (int x = 0; x < 4; x++) acc[i][j][x] = 0.f;
        }

        uint32_t abase = smb + MM_SM_A + (q % 3) * 32768;
        uint32_t bhB = smb + MM_SM_B + (c * 2) * 16384;
        uint32_t blB = bhB + 16384;
#pragma unroll
        for (int ks = 0; ks < 4; ks++) {
            uint32_t ah[2][4], al[2][4];
#pragma unroll
            for (int mt = 0; mt < 2; mt++) {
                int r = m0 + mt * 16 + (gA_r << 3) + gi;
                uint32_t off = sw128((uint32_t)(r * 128 + (ks * 2 + gA_c) * 16));
                ldsm_x4(ah[mt], abase + off);
                ldsm_x4(al[mt], abase + 16384 + off);
            }
            uint32_t bh[4][2], bl[4][2];
#pragma unroll
            for (int p = 0; p < 2; p++) {
                int n = n0 + (p << 4) + (gB_r << 3) + gi;
                uint32_t off = sw128((uint32_t)(n * 128 + (ks * 2 + gB_c) * 16));
                uint32_t t4[4];
                ldsm_x4(t4, bhB + off);
                bh[2 * p][0] = t4[0]; bh[2 * p][1] = t4[1];
                bh[2 * p + 1][0] = t4[2]; bh[2 * p + 1][1] = t4[3];
                ldsm_x4(t4, blB + off);
                bl[2 * p][0] = t4[0]; bl[2 * p][1] = t4[1];
                bl[2 * p + 1][0] = t4[2]; bl[2 * p + 1][1] = t4[3];
            }
#pragma unroll
            for (int mt = 0; mt < 2; mt++)
#pragma unroll
                for (int nt = 0; nt < 4; nt++) {
                    mma_f16(acc[mt][nt], ah[mt], bh[nt][0], bh[nt][1]);
                    mma_f16(acc[mt][nt], ah[mt], bl[nt][0], bl[nt][1]);
                    mma_f16(acc[mt][nt], al[mt], bh[nt][0], bh[nt][1]);
                }
        }

        if (c == KCH - 1) {
            int m0g = (blockIdx.x + k * GRID_P) * 128;
            if (EPI == 5) {
#pragma unroll
                for (int mt = 0; mt < 2; mt++)
#pragma unroll
                    for (int hf = 0; hf < 2; hf++) {
                        int r = m0 + mt * 16 + (lane >> 2) + hf * 8;
#pragma unroll
                        for (int nt = 0; nt < 4; nt++)
#pragma unroll
                            for (int e = 0; e < 2; e++) {
                                int n = n0 + nt * 8 + (lane & 3) * 2 + e;
                                if (n < 64)
                                    tS[r * 65 + n] =
                                        fmaxf(acc[mt][nt][hf * 2 + e] + b1s[n], 0.f);
                            }
                    }
                __syncthreads();
#pragma unroll
                for (int j = 0; j < 3; j++) {
                    int idx = tid + j * 512;
                    int r = idx / CN, cc = idx - r * CN;
                    int gm = m0g + r;
                    if (gm < M) {
                        float s = b2s[cc];
#pragma unroll 16
                        for (int n = 0; n < 64; n++)
                            s += tS[r * 65 + n] * w2s[n * CN + cc];
                        outF[(size_t)gm * CN + cc] = s;
                    }
                }
                __syncthreads();
            } else {
#pragma unroll
                for (int mt = 0; mt < 2; mt++)
#pragma unroll
                    for (int hf = 0; hf < 2; hf++) {
                        int gm = m0g + m0 + mt * 16 + (lane >> 2) + hf * 8;
                        if (gm >= M) continue;
#pragma unroll
                        for (int nt = 0; nt < 4; nt++)
#pragma unroll
                            for (int e = 0; e < 2; e++) {
                                int n = n0 + nt * 8 + (lane & 3) * 2 + e;
                                float v = acc[mt][nt][hf * 2 + e];
                                if (EPI == 0) {
                                    v = fmaxf(v + b1s[n], 0.f);
                                    __half h = __float2half_rn(v);
                                    outH[(size_t)gm * 128 + n] = h;
                                    outL[(size_t)gm * 128 + n] =
                                        __float2half_rn(v - __half2float(h));
                                } else if (EPI == 1) {
                                    outF[(size_t)gm * 128 + n] = v;
                                } else {
                                    outH[(size_t)gm * 128 + n] = __float2half_rn(v);
                                }
                            }
                    }
            }
        }
    }
}

// ---------------------------------------------------------------------------
// Edge MLP v6: CSR-ordered tiles, sync-free fills.
// src rows bulk (128), Q rows bulk deduped (~13), ea bulk (1). One mbar/stage.
// ---------------------------------------------------------------------------
#define ESM_W1A  0                       // 2 blocks sw128, 32768
#define ESM_W1C  32768                   // 8192
#define ESM_SRC  40960                   // 2 x 34816
#define ESM_Q    110592                  // 2 x 32768
#define ESM_EA   176128                  // 2 x 8192
#define ESM_B1   192512                  // 512
#define ESM_W2   193024                  // 2048
#define ESM_B2   195072                  // 16
#define ESM_OP   195088                  // 8192
#define ESM_MBAR 203280                  // 16
#define ESM_END  203296

__global__ __launch_bounds__(512, 1)
void k_edge(const __half* __restrict__ h16, const __half* __restrict__ Q,
            const __half* __restrict__ eap,
            const __half* __restrict__ w1a, const __half* __restrict__ w1c,
            const int* __restrict__ csrc, const int* __restrict__ ceid,
            const unsigned char* __restrict__ segsG, const int* __restrict__ utgt,
            const int* __restrict__ nsegG,
            const float* __restrict__ b1, const float* __restrict__ W2,
            const float* __restrict__ b2, float* __restrict__ out)
{
    extern __shared__ char sm[];
    uint32_t smb = (uint32_t)__cvta_generic_to_shared(sm);
    float* b1s = (float*)(sm + ESM_B1);
    float* w2s = (float*)(sm + ESM_W2);
    float* b2s = (float*)(sm + ESM_B2);
    float* opart = (float*)(sm + ESM_OP);

    const int tid  = threadIdx.x;
    const int lane = tid & 31;
    const int w    = tid >> 5;
    const int wm   = w & 3, wn = w >> 2;
    const int m0   = wm * 32, n0 = wn * 32;

    if (tid < 128) b1s[tid] = b1[tid];
    if (tid < 512) w2s[tid] = W2[tid];
    if (tid < 4)   b2s[tid] = b2[tid];
    if (tid == 0) {
        mbar_init(smb + ESM_MBAR, 1);
        mbar_init(smb + ESM_MBAR + 8, 1);
    }

    int nLocal = 0;
    for (int t = blockIdx.x; t < NT_EDGE; t += GRID_P) nLocal++;
    if (nLocal == 0) return;

    // resident B: W1a 2 sw128 blocks + W1c compact
    for (int idx = tid; idx < 2048 + 512; idx += 512) {
        if (idx < 2048) {
            int b = idx >> 10, n = (idx >> 3) & 127, fc = idx & 7;
            cp16(smb + ESM_W1A + b * 16384 + sw128((uint32_t)(n * 128 + fc * 16)),
                 w1a + (size_t)n * 128 + b * 64 + fc * 8);
        } else {
            int i2 = idx - 2048, n = i2 >> 2, fc = i2 & 3;
            cp16(smb + ESM_W1C + n * 64 + fc * 16, w1c + (size_t)n * 32 + fc * 8);
        }
    }
    asm volatile("cp.async.commit_group;");
    __syncthreads();   // mbarrier init visible before bulk fills

    // sync-free fill of tile k into stage k&1
    auto fill = [&](int k) {
        int stage = k & 1;
        int tile = blockIdx.x + k * GRID_P;
        int p0 = tile * 128;
        uint32_t bar = smb + ESM_MBAR + stage * 8;
        uint32_t sst = smb + ESM_SRC + stage * 34816;
        uint32_t qst = smb + ESM_Q + stage * 32768;
        if (tid == 0) {
            int ns = __ldg(&nsegG[tile]);
            mbar_expect(bar, (uint32_t)(128 + ns) * 256 + 8192);
        }
        if (tid < 128) {
            int s = __ldg(&csrc[p0 + tid]);
            bulk_ld(sst + (uint32_t)tid * 272, h16 + (size_t)s * HH, 256, bar);
        } else if (tid < 256) {
            int j = tid - 128;
            int ns = __ldg(&nsegG[tile]);
            if (j < ns) {
                int t = __ldg(&utgt[p0 + j]);
                bulk_ld(qst + (uint32_t)j * 256, Q + (size_t)t * HH, 256, bar);
            }
        } else if (tid == 256) {
            bulk_ld(smb + ESM_EA + stage * 8192, eap + (size_t)p0 * FE, 8192, bar);
        }
    };

    fill(0);
    if (nLocal > 1) fill(1);
    asm volatile("cp.async.wait_group 0;" ::: "memory");   // W1 resident
    __syncthreads();

    const int gi   = lane & 7;
    const int gA_r = (lane >> 3) & 1;
    const int gA_c = lane >> 4;
    const int gB_r = lane >> 4;
    const int gB_c = (lane >> 3) & 1;

    for (int k = 0; k < nLocal; k++) {
        const int kb = k & 1;
        const int tile = blockIdx.x + k * GRID_P;
        const int p0 = tile * 128;
        const uint32_t sst = smb + ESM_SRC + kb * 34816;

        mbar_wait(smb + ESM_MBAR + kb * 8, (k >> 1) & 1);

        float acc[2][4][4];
#pragma unroll
        for (int i = 0; i < 2; i++)
#pragma unroll
            for (int j = 0; j < 4; j++)
#pragma unroll
                for (int x = 0; x < 4; x++) acc[i][j][x] = 0.f;

        // chunks 0-1: h[src] @ W1a
#pragma unroll
        for (int c = 0; c < 2; c++) {
            uint32_t abase = sst + (uint32_t)(c * 128);
            uint32_t bbase = smb + ESM_W1A + c * 16384;
#pragma unroll
            for (int ks = 0; ks < 4; ks++) {
                uint32_t a[2][4];
#pragma unroll
                for (int mt = 0; mt < 2; mt++) {
                    int r = m0 + mt * 16 + (gA_r << 3) + gi;
                    ldsm_x4(a[mt], abase + (uint32_t)(r * 272 + (ks * 2 + gA_c) * 16));
                }
                uint32_t bh[4][2];
#pragma unroll
                for (int p = 0; p < 2; p++) {
                    int n = n0 + (p << 4) + (gB_r << 3) + gi;
                    uint32_t t4[4];
                    ldsm_x4(t4, bbase + sw128((uint32_t)(n * 128 + (ks * 2 + gB_c) * 16)));
                    bh[2 * p][0] = t4[0]; bh[2 * p][1] = t4[1];
                    bh[2 * p + 1][0] = t4[2]; bh[2 * p + 1][1] = t4[3];
                }
#pragma unroll
                for (int mt = 0; mt < 2; mt++)
#pragma unroll
                    for (int nt = 0; nt < 4; nt++)
                        mma_f16(acc[mt][nt], a[mt], bh[nt][0], bh[nt][1]);
            }
        }

        // chunk ea: ea @ W1c
#pragma unroll
        for (int ks = 0; ks < 2; ks++) {
            uint32_t a[2][4];
#pragma unroll
            for (int mt = 0; mt < 2; mt++) {
                int r = m0 + mt * 16 + (gA_r << 3) + gi;
                ldsm_x4(a[mt], smb + ESM_EA + kb * 8192
                              + (uint32_t)(r * 64 + (ks * 2 + gA_c) * 16));
            }
            uint32_t bh[4][2];
#pragma unroll
            for (int p = 0; p < 2; p++) {
                int n = n0 + (p << 4) + (gB_r << 3) + gi;
                uint32_t t4[4];
                ldsm_x4(t4, smb + ESM_W1C + (uint32_t)(n * 64 + (ks * 2 + gB_c) * 16));
                bh[2 * p][0] = t4[0]; bh[2 * p][1] = t4[1];
                bh[2 * p + 1][0] = t4[2]; bh[2 * p + 1][1] = t4[3];
            }
#pragma unroll
            for (int mt = 0; mt < 2; mt++)
#pragma unroll
                for (int nt = 0; nt < 4; nt++)
                    mma_f16(acc[mt][nt], a[mt], bh[nt][0], bh[nt][1]);
        }

        // ----- epilogue: + Q[seg] + b1, relu, 128x4 GEMM, reduce, scatter -----
        {
            float p[4][4];
#pragma unroll
            for (int i = 0; i < 4; i++)
#pragma unroll
                for (int j = 0; j < 4; j++) p[i][j] = 0.f;

#pragma unroll
            for (int mt = 0; mt < 2; mt++)
#pragma unroll
                for (int hf = 0; hf < 2; hf++) {
                    int ri = mt * 2 + hf;
                    int r = m0 + mt * 16 + (lane >> 2) + hf * 8;
                    int seg = (int)__ldg(&segsG[p0 + r]);
                    const __half* qrow = (const __half*)(sm + ESM_Q + kb * 32768
                                                          + seg * 256);
#pragma unroll
                    for (int nt = 0; nt < 4; nt++) {
                        int colg = n0 + nt * 8 + (lane & 3) * 2;
                        __half2 qv = *(const __half2*)&qrow[colg];
                        float2 qf = __half22float2(qv);
#pragma unroll
                        for (int e = 0; e < 2; e++) {
                            float qe = e ? qf.y : qf.x;
                            float h1 = fmaxf(acc[mt][nt][hf * 2 + e] + qe
                                             + b1s[colg + e], 0.f);
#pragma unroll
                            for (int cc = 0; cc < 4; cc++)
                                p[ri][cc] += h1 * w2s[(colg + e) * 4 + cc];
                        }
                    }
                }
#pragma unroll
            for (int i = 0; i < 4; i++)
#pragma unroll
                for (int cc = 0; cc < 4; cc++) {
                    p[i][cc] += __shfl_xor_sync(0xffffffffu, p[i][cc], 1);
                    p[i][cc] += __shfl_xor_sync(0xffffffffu, p[i][cc], 2);
                }
            if ((lane & 3) == 0) {
#pragma unroll
                for (int mt = 0; mt < 2; mt++)
#pragma unroll
                    for (int hf = 0; hf < 2; hf++) {
                        int r = m0 + mt * 16 + (lane >> 2) + hf * 8;
#pragma unroll
                        for (int cc = 0; cc < 4; cc++)
                            opart[wn * 512 + r * 4 + cc] = p[mt * 2 + hf][cc];
                    }
            }
            __syncthreads();
            {
                int r = tid >> 2, cc = tid & 3;
                int eid = __ldg(&ceid[p0 + r]);
                float s = opart[tid] + opart[512 + tid] + opart[1024 + tid]
                        + opart[1536 + tid] + b2s[cc];
                out[(size_t)eid * 4 + cc] = s;
            }
            __syncthreads();   // stage kb + opart free
        }

        if (k + 2 < nLocal) fill(k + 2);
    }
}

// ---------------------------------------------------------------------------
extern "C" void kernel_launch(void* const* d_in, const int* in_sizes, int n_in,
                              void* d_out, int out_size)
{
    const float* x   = (const float*)d_in[0];
    const int*   ei  = (const int*)  d_in[1];
    const float* ea  = (const float*)d_in[2];
    const float* We  = (const float*)d_in[3];
    const float* be  = (const float*)d_in[4];
    const float* Wc1 = (const float*)d_in[5];
    const float* bc1 = (const float*)d_in[6];
    const float* Wc2 = (const float*)d_in[7];
    const float* bc2 = (const float*)d_in[8];
    const float* Wn1 = (const float*)d_in[9];
    const float* bn1 = (const float*)d_in[10];
    const float* Wn2 = (const float*)d_in[11];
    const float* bn2 = (const float*)d_in[12];
    const float* We1 = (const float*)d_in[13];
    const float* be1 = (const float*)d_in[14];
    const float* We2 = (const float*)d_in[15];
    const float* be2 = (const float*)d_in[16];

    const int* row = ei;
    const int* col = ei + EE;

    float* out_node = (float*)d_out;
    float* out_edge = out_node + (size_t)NN * CN;

    float *pxw, *pdinv;
    int *pdeg, *ppart, *prs, *pcur, *pbsum, *pboff, *pcsrc, *pceid, *pctgt;
    int *putgt, *pnseg;
    unsigned char* psegs;
    __half *pxh, *pxl, *phh, *phl, *pQ, *pea16, *peap, *pw1a, *pw1c;
    __half *wWeH, *wWeL, *wC1H, *wC1L, *wC2H, *wC2L, *wN1H, *wN1L, *w1bH, *w1bL;
    cudaGetSymbolAddress((void**)&pxw,   g_xw);
    cudaGetSymbolAddress((void**)&pdinv, g_dinv);
    cudaGetSymbolAddress((void**)&pdeg,  g_deg);
    cudaGetSymbolAddress((void**)&ppart, g_part);
    cudaGetSymbolAddress((void**)&prs,   g_rs);
    cudaGetSymbolAddress((void**)&pcur,  g_cur);
    cudaGetSymbolAddress((void**)&pbsum, g_blksum);
    cudaGetSymbolAddress((void**)&pboff, g_blkoff);
    cudaGetSymbolAddress((void**)&pcsrc, g_csrc);
    cudaGetSymbolAddress((void**)&pceid, g_ceid);
    cudaGetSymbolAddress((void**)&pctgt, g_ctgt);
    cudaGetSymbolAddress((void**)&psegs, g_segs);
    cudaGetSymbolAddress((void**)&putgt, g_utgt);
    cudaGetSymbolAddress((void**)&pnseg, g_nseg);
    cudaGetSymbolAddress((void**)&pxh,   g_xh);
    cudaGetSymbolAddress((void**)&pxl,   g_xl);
    cudaGetSymbolAddress((void**)&phh,   g_hh);
    cudaGetSymbolAddress((void**)&phl,   g_hl);
    cudaGetSymbolAddress((void**)&pQ,    g_Q);
    cudaGetSymbolAddress((void**)&pea16, g_ea16);
    cudaGetSymbolAddress((void**)&peap,  g_eap);
    cudaGetSymbolAddress((void**)&pw1a,  g_w1a16);
    cudaGetSymbolAddress((void**)&pw1c,  g_w1c16);
    cudaGetSymbolAddress((void**)&wWeH,  g_wWe_h);
    cudaGetSymbolAddress((void**)&wWeL,  g_wWe_l);
    cudaGetSymbolAddress((void**)&wC1H,  g_wC1_h);
    cudaGetSymbolAddress((void**)&wC1L,  g_wC1_l);
    cudaGetSymbolAddress((void**)&wC2H,  g_wC2_h);
    cudaGetSymbolAddress((void**)&wC2L,  g_wC2_l);
    cudaGetSymbolAddress((void**)&wN1H,  g_wN1_h);
    cudaGetSymbolAddress((void**)&wN1L,  g_wN1_l);
    cudaGetSymbolAddress((void**)&w1bH,  g_w1b_h);
    cudaGetSymbolAddress((void**)&w1bL,  g_w1b_l);

    static bool attr_set = false;
    if (!attr_set) {
        cudaFuncSetAttribute(k_edge, cudaFuncAttributeMaxDynamicSharedMemorySize, ESM_END);
        cudaFuncSetAttribute(k_mm<1,0>, cudaFuncAttributeMaxDynamicSharedMemorySize, MM_SM_END);
        cudaFuncSetAttribute(k_mm<2,1>, cudaFuncAttributeMaxDynamicSharedMemorySize, MM_SM_END);
        cudaFuncSetAttribute(k_mm<2,4>, cudaFuncAttributeMaxDynamicSharedMemorySize, MM_SM_END);
        cudaFuncSetAttribute(k_mm<2,5>, cudaFuncAttributeMaxDynamicSharedMemorySize, MM_SM_END);
        attr_set = true;
    }

    const int T = 256;

    // degrees + norm + CSR (by target) + metadata + ea permute
    k_deg_init<<<(NN + T - 1) / T, T>>>(pdeg);
    k_deg_edges<<<(EE + T - 1) / T, T>>>(col, pdeg);
    k_dinv<<<(NN + T - 1) / T, T>>>(pdeg, pdinv);
    k_scan1<<<NBLK, 256>>>(pdeg, ppart, pbsum);
    k_scan2<<<1, 256>>>(pbsum, pboff);
    k_scan3<<<NBLK, 256>>>(ppart, pboff, prs, pcur);
    k_fill<<<(EE + T - 1) / T, T>>>(row, col, pcur, pcsrc, pceid, pctgt);
    k_pad<<<1, 256>>>(pcsrc, pceid, pctgt);
    k_meta<<<(NT_EDGE * 32 + T - 1) / T, T>>>(pctgt, psegs, putgt, pnseg);
    {
        size_t n8 = (size_t)EE * FE / 8;
        k_tof16_v<<<(int)((n8 + T - 1) / T), T>>>((const float4*)ea, (uint4*)pea16, n8);
    }
    k_permea<<<(int)(((size_t)EPAD * 4 + T - 1) / T), T>>>(pceid, pea16, peap);

    // conversions / splits
    k_w1a16<<<(128 * 128 + T - 1) / T, T>>>(We1, pw1a);
    k_w1c16<<<(128 * 32 + T - 1) / T, T>>>(We1, pw1c);
    k_splitA<<<(int)(((size_t)NN * FN + T - 1) / T), T>>>(x, pxh, pxl, (size_t)NN * FN);
    k_splitWt<<<(128 * 64 + T - 1) / T, T>>>(We, wWeH, wWeL, 64, 128);
    k_splitWt<<<(128 * 128 + T - 1) / T, T>>>(Wc1, wC1H, wC1L, 128, 128);
    k_splitWt<<<(128 * 128 + T - 1) / T, T>>>(Wc2, wC2H, wC2L, 128, 128);
    k_splitWt<<<(128 * 128 + T - 1) / T, T>>>(Wn1, wN1H, wN1L, 128, 64);
    k_splitWt<<<(128 * 128 + T - 1) / T, T>>>(We1 + 128 * 128, w1bH, w1bL, 128, 128);

    // embed: h = relu(x @ We + be)  -> hh/hl
    k_mm<1,0><<<GRID_P, 512, MM_SM_END>>>(pxh, pxl, wWeH, wWeL, be,
                                          nullptr, phh, phl, nullptr, nullptr, NN, 128);
    // conv1 + pull
    k_mm<2,1><<<GRID_P, 512, MM_SM_END>>>(phh, phl, wC1H, wC1L, nullptr,
                                          pxw, nullptr, nullptr, nullptr, nullptr, NN, 128);
    k_pull<<<(NN * 32 + T - 1) / T, T>>>(pxw, pcsrc, prs, pdeg, pdinv, bc1, phh, phl);
    // conv2 + pull
    k_mm<2,1><<<GRID_P, 512, MM_SM_END>>>(phh, phl, wC2H, wC2L, nullptr,
                                          pxw, nullptr, nullptr, nullptr, nullptr, NN, 128);
    k_pull<<<(NN * 32 + T - 1) / T, T>>>(pxw, pcsrc, prs, pdeg, pdinv, bc2, phh, phl);

    // Q = h @ W1b (fp16 out; b1 added in k_edge epilogue)
    k_mm<2,4><<<GRID_P, 512, MM_SM_END>>>(phh, phl, w1bH, w1bL, nullptr,
                                          nullptr, pQ, nullptr, nullptr, nullptr, NN, 128);

    // fused node head
    k_mm<2,5><<<GRID_P, 512, MM_SM_END>>>(phh, phl, wN1H, wN1L, bn1,
                                          out_node, nullptr, nullptr, Wn2, bn2, NN, 64);

    // edge MLP v6
    k_edge<<<GRID_P, 512, ESM_END>>>(phh, pQ, peap, pw1a, pw1c,
                                     pcsrc, pceid, psegs, putgt, pnseg,
                                     be1, We2, be2, out_edge);
}

// round 17
// speedup vs baseline: 1.1108x; 1.1108x over previous
#include <cuda_runtime.h>
#include <cuda_fp16.h>
#include <cstdint>

#define NN 100000
#define EE 1000000
#define HH 128
#define FN 64
#define FE 32
#define CN 12
#define CE 4
#define KTOT 288
#define NT_EDGE ((EE + 127) / 128)   // 7813
#define GRID_P 148
#define NBLK ((NN + 255) / 256)      // 391

// ---------------------------------------------------------------------------
// Scratch (device globals — no cudaMalloc allowed)
// ---------------------------------------------------------------------------
__device__ float g_xw [(size_t)NN * HH];
__device__ float g_dinv[NN];
__device__ int   g_deg [NN];
__device__ int   g_part[NN];
__device__ int   g_rs  [NN];
__device__ int   g_cur [NN];
__device__ int   g_blksum[NBLK + 1];
__device__ int   g_blkoff[NBLK + 1];
__device__ int   g_csr [EE];

__device__ __align__(16) __half g_xh [(size_t)NN * FN];
__device__ __align__(16) __half g_xl [(size_t)NN * FN];
__device__ __align__(16) __half g_hh [(size_t)NN * HH];
__device__ __align__(16) __half g_hl [(size_t)NN * HH];
__device__ __align__(16) __half g_ea16[(size_t)EE * FE];
__device__ __align__(16) __half g_w1h [HH * KTOT];

// node-path weight transposes (hi/lo), N padded to 128 rows
__device__ __align__(16) __half g_wWe_h[128 * 64],  g_wWe_l[128 * 64];
__device__ __align__(16) __half g_wC1_h[128 * 128], g_wC1_l[128 * 128];
__device__ __align__(16) __half g_wC2_h[128 * 128], g_wC2_l[128 * 128];
__device__ __align__(16) __half g_wN1_h[128 * 128], g_wN1_l[128 * 128];

// ---------------------------------------------------------------------------
// Degree / normalization / CSR build
// ---------------------------------------------------------------------------
__global__ void k_deg_init(int* __restrict__ deg) {
    int i = blockIdx.x * blockDim.x + threadIdx.x;
    if (i < NN) deg[i] = 0;
}
__global__ void k_deg_edges(const int* __restrict__ col, int* __restrict__ deg) {
    int e = blockIdx.x * blockDim.x + threadIdx.x;
    if (e < EE) atomicAdd(&deg[col[e]], 1);
}
__global__ void k_dinv(const int* __restrict__ deg, float* __restrict__ dinv) {
    int i = blockIdx.x * blockDim.x + threadIdx.x;
    if (i < NN) dinv[i] = rsqrtf((float)(deg[i] + 1));
}

__global__ void k_scan1(const int* __restrict__ deg, int* __restrict__ part,
                        int* __restrict__ blksum)
{
    __shared__ int s[256];
    int tid = threadIdx.x;
    int i = blockIdx.x * 256 + tid;
    int v = (i < NN) ? deg[i] : 0;
    s[tid] = v;
    __syncthreads();
#pragma unroll
    for (int off = 1; off < 256; off <<= 1) {
        int x = (tid >= off) ? s[tid - off] : 0;
        __syncthreads();
        s[tid] += x;
        __syncthreads();
    }
    if (i < NN) part[i] = s[tid] - v;
    if (tid == 255) blksum[blockIdx.x] = s[255];
}
__global__ void k_scan2(const int* __restrict__ blksum, int* __restrict__ blkoff)
{
    if (threadIdx.x == 0) {
        int acc = 0;
        for (int b = 0; b < NBLK; b++) { blkoff[b] = acc; acc += blksum[b]; }
    }
}
__global__ void k_scan3(const int* __restrict__ part, const int* __restrict__ blkoff,
                        int* __restrict__ rs, int* __restrict__ cur)
{
    int i = blockIdx.x * blockDim.x + threadIdx.x;
    if (i < NN) {
        int v = part[i] + blkoff[i >> 8];
        rs[i] = v;
        cur[i] = v;
    }
}
__global__ void k_fill(const int* __restrict__ row, const int* __restrict__ col,
                       int* __restrict__ cur, int* __restrict__ csr)
{
    int e = blockIdx.x * blockDim.x + threadIdx.x;
    if (e < EE) {
        int pos = atomicAdd(&cur[col[e]], 1);
        csr[pos] = row[e];
    }
}

// ---------------------------------------------------------------------------
// splits / conversions
// ---------------------------------------------------------------------------
__global__ void k_splitA(const float* __restrict__ in, __half* __restrict__ hi,
                         __half* __restrict__ lo, size_t n)
{
    size_t i = (size_t)blockIdx.x * blockDim.x + threadIdx.x;
    if (i < n) {
        float x = in[i];
        __half h = __float2half_rn(x);
        hi[i] = h;
        lo[i] = __float2half_rn(x - __half2float(h));
    }
}

__global__ void k_splitWt(const float* __restrict__ W, __half* __restrict__ hi,
                          __half* __restrict__ lo, int K, int Nn)
{
    int i = blockIdx.x * blockDim.x + threadIdx.x;
    if (i < 128 * K) {
        int n = i / K, k = i % K;
        float x = (n < Nn) ? W[(size_t)k * Nn + n] : 0.f;
        __half h = __float2half_rn(x);
        hi[i] = h;
        lo[i] = __float2half_rn(x - __half2float(h));
    }
}

__global__ void k_tof16_v(const float4* __restrict__ in, uint4* __restrict__ o, size_t n8)
{
    size_t i = (size_t)blockIdx.x * blockDim.x + threadIdx.x;
    if (i >= n8) return;
    float4 a = in[i * 2];
    float4 b = in[i * 2 + 1];
    __half2 h[4];
    h[0] = __floats2half2_rn(a.x, a.y);
    h[1] = __floats2half2_rn(a.z, a.w);
    h[2] = __floats2half2_rn(b.x, b.y);
    h[3] = __floats2half2_rn(b.z, b.w);
    o[i] = *reinterpret_cast<const uint4*>(h);
}

// W1 [K=288][N=128] -> W1t [N=128][K=288] fp16 (edge MLP)
__global__ void k_w1t16(const float* __restrict__ W1, __half* __restrict__ o)
{
    int i = blockIdx.x * blockDim.x + threadIdx.x;
    if (i < HH * KTOT) {
        int n = i / KTOT, k = i % KTOT;
        o[i] = __float2half_rn(W1[(size_t)k * HH + n]);
    }
}

// ---------------------------------------------------------------------------
// CSR pull aggregation: warp per node.
// ---------------------------------------------------------------------------
__global__ __launch_bounds__(256)
void k_pull(const float* __restrict__ xw, const int* __restrict__ csr,
            const int* __restrict__ rs, const int* __restrict__ deg,
            const float* __restrict__ dinv, const float* __restrict__ bias,
            __half* __restrict__ hh, __half* __restrict__ hl)
{
    int wid = (blockIdx.x * 256 + threadIdx.x) >> 5;
    int lane = threadIdx.x & 31;
    if (wid >= NN) return;
    int t = wid;
    float dt = dinv[t];
    float d2 = dt * dt;
    const float4* xw4 = (const float4*)xw;
    float4 a = xw4[(size_t)t * 32 + lane];
    float4 acc;
    acc.x = a.x * d2; acc.y = a.y * d2; acc.z = a.z * d2; acc.w = a.w * d2;

    int start = rs[t];
    int n = deg[t];
    for (int i = 0; i < n; i++) {
        int s = __ldg(&csr[start + i]);
        float c = dinv[s] * dt;
        float4 v = xw4[(size_t)s * 32 + lane];
        acc.x += v.x * c; acc.y += v.y * c; acc.z += v.z * c; acc.w += v.w * c;
    }

    float4 b = *(const float4*)&bias[lane * 4];
    float h0 = fmaxf(acc.x + b.x, 0.f);
    float h1 = fmaxf(acc.y + b.y, 0.f);
    float h2 = fmaxf(acc.z + b.z, 0.f);
    float h3 = fmaxf(acc.w + b.w, 0.f);

    __half2 hi[2], lo[2];
    hi[0] = __floats2half2_rn(h0, h1);
    hi[1] = __floats2half2_rn(h2, h3);
    float l0 = h0 - __half2float(__low2half(hi[0]));
    float l1 = h1 - __half2float(__high2half(hi[0]));
    float l2 = h2 - __half2float(__low2half(hi[1]));
    float l3 = h3 - __half2float(__high2half(hi[1]));
    lo[0] = __floats2half2_rn(l0, l1);
    lo[1] = __floats2half2_rn(l2, l3);
    *(uint2*)&hh[(size_t)t * HH + lane * 4] = *reinterpret_cast<const uint2*>(hi);
    *(uint2*)&hl[(size_t)t * HH + lane * 4] = *reinterpret_cast<const uint2*>(lo);
}

// ---------------------------------------------------------------------------
// mma helpers
// ---------------------------------------------------------------------------
__device__ __forceinline__ uint32_t sw128(uint32_t byte_off) {
    return byte_off ^ ((byte_off >> 3) & 0x70);
}
__device__ __forceinline__ void ldsm_x4(uint32_t (&r)[4], uint32_t addr) {
    asm volatile("ldmatrix.sync.aligned.m8n8.x4.shared.b16 {%0,%1,%2,%3}, [%4];"
                 : "=r"(r[0]), "=r"(r[1]), "=r"(r[2]), "=r"(r[3]) : "r"(addr));
}
__device__ __forceinline__ void mma_f16(float (&d)[4], const uint32_t (&a)[4],
                                        uint32_t b0, uint32_t b1) {
    asm volatile("mma.sync.aligned.m16n8k16.row.col.f32.f16.f16.f32 "
                 "{%0,%1,%2,%3},{%4,%5,%6,%7},{%8,%9},{%0,%1,%2,%3};"
                 : "+f"(d[0]), "+f"(d[1]), "+f"(d[2]), "+f"(d[3])
                 : "r"(a[0]), "r"(a[1]), "r"(a[2]), "r"(a[3]), "r"(b0), "r"(b1));
}
__device__ __forceinline__ void cp16(uint32_t saddr, const void* gaddr) {
    asm volatile("cp.async.cg.shared.global [%0], [%1], 16;" :: "r"(saddr), "l"(gaddr));
}
__device__ __forceinline__ void bulk_ld(uint32_t dst, const void* src, uint32_t bytes,
                                        uint32_t mbar) {
    asm volatile("cp.async.bulk.shared::cluster.global.mbarrier::complete_tx::bytes "
                 "[%0], [%1], %2, [%3];"
                 :: "r"(dst), "l"(src), "r"(bytes), "r"(mbar) : "memory");
}
__device__ __forceinline__ void mbar_init(uint32_t mbar, uint32_t cnt) {
    asm volatile("mbarrier.init.shared.b64 [%0], %1;" :: "r"(mbar), "r"(cnt) : "memory");
}
__device__ __forceinline__ void mbar_expect(uint32_t mbar, uint32_t bytes) {
    asm volatile("mbarrier.arrive.expect_tx.shared.b64 _, [%0], %1;"
                 :: "r"(mbar), "r"(bytes) : "memory");
}
__device__ __forceinline__ void mbar_wait(uint32_t mbar, uint32_t parity) {
    uint32_t done = 0;
    while (!done) {
        asm volatile("{\n\t.reg .pred p;\n\t"
                     "mbarrier.try_wait.parity.shared::cta.b64 p, [%1], %2;\n\t"
                     "selp.b32 %0, 1, 0, p;\n\t}"
                     : "=r"(done) : "r"(mbar), "r"(parity) : "memory");
    }
}

// ---------------------------------------------------------------------------
// Unified node-path GEMM: persistent, split-fp16 3-pass.
// EPI: 0=relu+split  1=plain fp32 out  5=fused node head (N=64 -> 12 logits)
// ---------------------------------------------------------------------------
#define MM_SM_B   0
#define MM_SM_A   65536
#define MM_SM_BIAS (65536 + 3 * 32768)      // 163840, 512 B
#define MM_SM_TS  (MM_SM_BIAS + 512)        // 164352, 128x65 f = 33280
#define MM_SM_W2  (MM_SM_TS + 33280)        // 197632, 64x12 f = 3072
#define MM_SM_B2  (MM_SM_W2 + 3072)         // 200704, 48
#define MM_SM_END (MM_SM_B2 + 64)           // 200768

template<int KCH, int EPI>
__global__ __launch_bounds__(512, 1)
void k_mm(const __half* __restrict__ Ah, const __half* __restrict__ Al,
          const __half* __restrict__ Bth, const __half* __restrict__ Btl,
          const float* __restrict__ bias,
          float* __restrict__ outF,
          __half* __restrict__ outH, __half* __restrict__ outL,
          const float* __restrict__ W2h, const float* __restrict__ b2h,
          int M, int Nn)
{
    constexpr int K = KCH * 64;
    extern __shared__ char sm[];
    uint32_t smb = (uint32_t)__cvta_generic_to_shared(sm);
    float* b1s = (float*)(sm + MM_SM_BIAS);
    float* tS  = (float*)(sm + MM_SM_TS);
    float* w2s = (float*)(sm + MM_SM_W2);
    float* b2s = (float*)(sm + MM_SM_B2);

    const int tid  = threadIdx.x;
    const int lane = tid & 31;
    const int w    = tid >> 5;
    const int wm   = w & 3, wn = w >> 2;
    const int m0   = wm * 32, n0 = wn * 32;

    const int NT = (M + 127) / 128;
    int nLocal = 0;
    for (int t = blockIdx.x; t < NT; t += GRID_P) nLocal++;
    if (nLocal == 0) return;
    const int totalQ = nLocal * KCH;

    for (int idx = tid; idx < 2 * KCH * 1024; idx += 512) {
        int b = idx >> 10, rem = idx & 1023;
        int n = rem >> 3, fc = rem & 7;
        int cb = b >> 1, hl = b & 1;
        const __half* src = (hl ? Btl : Bth) + (size_t)n * K + cb * 64 + fc * 8;
        cp16(smb + MM_SM_B + b * 16384 + sw128((uint32_t)(n * 128 + fc * 16)), src);
    }
    asm volatile("cp.async.commit_group;");

    if (tid < 128) b1s[tid] = (bias && tid < Nn) ? bias[tid] : 0.f;
    if (EPI == 5) {
        for (int i = tid; i < 64 * CN; i += 512) w2s[i] = W2h[i];
        if (tid < CN) b2s[tid] = b2h[tid];
    }
    __syncthreads();

    auto fill = [&](int q) {
        int k = q / KCH, c = q - k * KCH;
        int m0g = (blockIdx.x + k * GRID_P) * 128;
        uint32_t abase = smb + MM_SM_A + (q % 3) * 32768;
#pragma unroll
        for (int it = 0; it < 2; it++) {
            int idx = tid + it * 512;
            int fr = idx >> 3, fc = idx & 7;
            int gm = min(m0g + fr, M - 1);
            size_t so = (size_t)gm * K + c * 64 + fc * 8;
            uint32_t d = sw128((uint32_t)(fr * 128 + fc * 16));
            cp16(abase + d, Ah + so);
            cp16(abase + 16384 + d, Al + so);
        }
        asm volatile("cp.async.commit_group;");
    };

    fill(0);
    if (totalQ > 1) fill(1);

    const int gi   = lane & 7;
    const int gA_r = (lane >> 3) & 1;
    const int gA_c = lane >> 4;
    const int gB_r = lane >> 4;
    const int gB_c = (lane >> 3) & 1;

    float acc[2][4][4];

    for (int q = 0; q < totalQ; q++) {
        int k = q / KCH, c = q - k * KCH;

        if (q + 1 < totalQ) { asm volatile("cp.async.wait_group 1;" ::: "memory"); }
        else                { asm volatile("cp.async.wait_group 0;" ::: "memory"); }
        __syncthreads();
        if (q + 2 < totalQ) fill(q + 2);

        if (c == 0) {
#pragma unroll
            for (int i = 0; i < 2; i++)
#pragma unroll
                for (int j = 0; j < 4; j++)
#pragma unroll
                    for (int x = 0; x < 4; x++) acc[i][j][x] = 0.f;
        }

        uint32_t abase = smb + MM_SM_A + (q % 3) * 32768;
        uint32_t bhB = smb + MM_SM_B + (c * 2) * 16384;
        uint32_t blB = bhB + 16384;
#pragma unroll
        for (int ks = 0; ks < 4; ks++) {
            uint32_t ah[2][4], al[2][4];
#pragma unroll
            for (int mt = 0; mt < 2; mt++) {
                int r = m0 + mt * 16 + (gA_r << 3) + gi;
                uint32_t off = sw128((uint32_t)(r * 128 + (ks * 2 + gA_c) * 16));
                ldsm_x4(ah[mt], abase + off);
                ldsm_x4(al[mt], abase + 16384 + off);
            }
            uint32_t bh[4][2], bl[4][2];
#pragma unroll
            for (int p = 0; p < 2; p++) {
                int n = n0 + (p << 4) + (gB_r << 3) + gi;
                uint32_t off = sw128((uint32_t)(n * 128 + (ks * 2 + gB_c) * 16));
                uint32_t t4[4];
                ldsm_x4(t4, bhB + off);
                bh[2 * p][0] = t4[0]; bh[2 * p][1] = t4[1];
                bh[2 * p + 1][0] = t4[2]; bh[2 * p + 1][1] = t4[3];
                ldsm_x4(t4, blB + off);
                bl[2 * p][0] = t4[0]; bl[2 * p][1] = t4[1];
                bl[2 * p + 1][0] = t4[2]; bl[2 * p + 1][1] = t4[3];
            }
#pragma unroll
            for (int mt = 0; mt < 2; mt++)
#pragma unroll
                for (int nt = 0; nt < 4; nt++) {
                    mma_f16(acc[mt][nt], ah[mt], bh[nt][0], bh[nt][1]);
                    mma_f16(acc[mt][nt], ah[mt], bl[nt][0], bl[nt][1]);
                    mma_f16(acc[mt][nt], al[mt], bh[nt][0], bh[nt][1]);
                }
        }

        if (c == KCH - 1) {
            int m0g = (blockIdx.x + k * GRID_P) * 128;
            if (EPI == 5) {
#pragma unroll
                for (int mt = 0; mt < 2; mt++)
#pragma unroll
                    for (int hf = 0; hf < 2; hf++) {
                        int r = m0 + mt * 16 + (lane >> 2) + hf * 8;
#pragma unroll
                        for (int nt = 0; nt < 4; nt++)
#pragma unroll
                            for (int e = 0; e < 2; e++) {
                                int n = n0 + nt * 8 + (lane & 3) * 2 + e;
                                if (n < 64)
                                    tS[r * 65 + n] =
                                        fmaxf(acc[mt][nt][hf * 2 + e] + b1s[n], 0.f);
                            }
                    }
                __syncthreads();
#pragma unroll
                for (int j = 0; j < 3; j++) {
                    int idx = tid + j * 512;
                    int r = idx / CN, cc = idx - r * CN;
                    int gm = m0g + r;
                    if (gm < M) {
                        float s = b2s[cc];
#pragma unroll 16
                        for (int n = 0; n < 64; n++)
                            s += tS[r * 65 + n] * w2s[n * CN + cc];
                        outF[(size_t)gm * CN + cc] = s;
                    }
                }
                __syncthreads();
            } else {
#pragma unroll
                for (int mt = 0; mt < 2; mt++)
#pragma unroll
                    for (int hf = 0; hf < 2; hf++) {
                        int gm = m0g + m0 + mt * 16 + (lane >> 2) + hf * 8;
                        if (gm >= M) continue;
#pragma unroll
                        for (int nt = 0; nt < 4; nt++)
#pragma unroll
                            for (int e = 0; e < 2; e++) {
                                int n = n0 + nt * 8 + (lane & 3) * 2 + e;
                                float v = acc[mt][nt][hf * 2 + e];
                                if (EPI == 0) {
                                    v = fmaxf(v + b1s[n], 0.f);
                                    __half h = __float2half_rn(v);
                                    outH[(size_t)gm * 128 + n] = h;
                                    outL[(size_t)gm * 128 + n] =
                                        __float2half_rn(v - __half2float(h));
                                } else {
                                    outF[(size_t)gm * 128 + n] = v;
                                }
                            }
                    }
            }
        }
    }
}

// ---------------------------------------------------------------------------
// Edge MLP (R13 version): persistent CTAs, W1t fp16 resident, gathered rows
// via cp.async.bulk (256B/row) into stride-272 unswizzled stages, mbarrier
// completion. 2 full-tile stages (src+tgt) + single-buffered ea tile.
// ---------------------------------------------------------------------------
#define STG_SZ   69632                  // src (128x272) + tgt (128x272)
#define ESM_B0   0                      // W1t blocks 0-3, sw128, 4x16384
#define ESM_B4   65536                  // W1t block 4 compact, 128x64B
#define ESM_ST   73728                  // 2 stages x 69632
#define ESM_EA   212992                 // ea tile, 128x64B
#define ESM_B1   221184                 // b1, 128 f
#define ESM_W2   221696                 // W2, 512 f
#define ESM_B2   223744                 // b2, 4 f
#define ESM_OP   223760                 // out partials [4][128][4] f
#define ESM_MBAR 231952                 // 3 mbarriers
#define ESM_END  231976

__global__ __launch_bounds__(512, 1)
void k_edge(const __half* __restrict__ h16, const __half* __restrict__ ea16,
            const __half* __restrict__ w1h,
            const int* __restrict__ row, const int* __restrict__ col,
            const float* __restrict__ b1, const float* __restrict__ W2,
            const float* __restrict__ b2, float* __restrict__ out)
{
    extern __shared__ char sm[];
    uint32_t smb = (uint32_t)__cvta_generic_to_shared(sm);
    float* b1s = (float*)(sm + ESM_B1);
    float* w2s = (float*)(sm + ESM_W2);
    float* b2s = (float*)(sm + ESM_B2);
    float* opart = (float*)(sm + ESM_OP);
    const uint32_t mb_st0 = smb + ESM_MBAR;
    const uint32_t mb_st1 = smb + ESM_MBAR + 8;
    const uint32_t mb_ea  = smb + ESM_MBAR + 16;

    const int tid  = threadIdx.x;
    const int lane = tid & 31;
    const int w    = tid >> 5;
    const int wm   = w & 3, wn = w >> 2;
    const int m0   = wm * 32, n0 = wn * 32;

    if (tid < 128) b1s[tid] = b1[tid];
    if (tid < 512) w2s[tid] = W2[tid];
    if (tid < 4)   b2s[tid] = b2[tid];
    if (tid == 0) { mbar_init(mb_st0, 1); mbar_init(mb_st1, 1); mbar_init(mb_ea, 1); }

    int nLocal = 0;
    for (int t = blockIdx.x; t < NT_EDGE; t += GRID_P) nLocal++;
    if (nLocal == 0) return;

    // resident B: blocks 0-3 sw128 (16KB each), block 4 compact (8KB, 64B rows)
    for (int idx = tid; idx < 4608; idx += 512) {
        uint32_t dst; const __half* src;
        if (idx < 4096) {
            int b = idx >> 10, n = (idx >> 3) & 127, fc = idx & 7;
            dst = ESM_B0 + b * 16384 + sw128((uint32_t)(n * 128 + fc * 16));
            src = w1h + (size_t)n * KTOT + b * 64 + fc * 8;
        } else {
            int i2 = idx - 4096, n = i2 >> 2, fc = i2 & 3;
            dst = ESM_B4 + n * 64 + fc * 16;
            src = w1h + (size_t)n * KTOT + 256 + fc * 8;
        }
        cp16(smb + dst, src);
    }
    asm volatile("cp.async.commit_group;");
    __syncthreads();   // mbarrier init + tables visible before bulk fills

    auto fill_st = [&](int k) {
        uint32_t st = smb + ESM_ST + (k & 1) * STG_SZ;
        uint32_t bar = (k & 1) ? mb_st1 : mb_st0;
        int e0 = (blockIdx.x + k * GRID_P) * 128;
        if (tid == 0) mbar_expect(bar, 65536);
        if (tid < 128) {
            int node = __ldg(&row[min(e0 + tid, EE - 1)]);
            bulk_ld(st + tid * 272, h16 + (size_t)node * HH, 256, bar);
        } else if (tid < 256) {
            int t2 = tid - 128;
            int node = __ldg(&col[min(e0 + t2, EE - 1)]);
            bulk_ld(st + 34816 + t2 * 272, h16 + (size_t)node * HH, 256, bar);
        }
    };
    auto fill_ea = [&](int k) {
        if (tid == 256) {
            int e0 = (blockIdx.x + k * GRID_P) * 128;
            int valid = min(128, EE - e0);
            uint32_t bytes = (uint32_t)valid * 64;
            mbar_expect(mb_ea, bytes);
            bulk_ld(smb + ESM_EA, ea16 + (size_t)e0 * FE, bytes, mb_ea);
        }
    };

    fill_st(0);
    if (nLocal > 1) fill_st(1);
    fill_ea(0);

    asm volatile("cp.async.wait_group 0;" ::: "memory");
    __syncthreads();   // B resident complete for all threads

    const int gi   = lane & 7;
    const int gA_r = (lane >> 3) & 1;
    const int gA_c = lane >> 4;
    const int gB_r = lane >> 4;
    const int gB_c = (lane >> 3) & 1;

    for (int k = 0; k < nLocal; k++) {
        const int kb = k & 1;
        const uint32_t st = smb + ESM_ST + kb * STG_SZ;
        const int e0 = (blockIdx.x + k * GRID_P) * 128;

        mbar_wait(kb ? mb_st1 : mb_st0, (k >> 1) & 1);

        float acc[2][4][4];
#pragma unroll
        for (int i = 0; i < 2; i++)
#pragma unroll
            for (int j = 0; j < 4; j++)
#pragma unroll
                for (int x = 0; x < 4; x++) acc[i][j][x] = 0.f;

#pragma unroll
        for (int c = 0; c < 4; c++) {
            uint32_t abase = st + ((c >= 2) ? 34816u : 0u) + (uint32_t)((c & 1) * 128);
            uint32_t bbase = smb + ESM_B0 + c * 16384;
#pragma unroll
            for (int ks = 0; ks < 4; ks++) {
                uint32_t a[2][4];
#pragma unroll
                for (int mt = 0; mt < 2; mt++) {
                    int r = m0 + mt * 16 + (gA_r << 3) + gi;
                    ldsm_x4(a[mt], abase + (uint32_t)(r * 272 + (ks * 2 + gA_c) * 16));
                }
                uint32_t bh[4][2];
#pragma unroll
                for (int p = 0; p < 2; p++) {
                    int n = n0 + (p << 4) + (gB_r << 3) + gi;
                    uint32_t t4[4];
                    ldsm_x4(t4, bbase + sw128((uint32_t)(n * 128 + (ks * 2 + gB_c) * 16)));
                    bh[2 * p][0] = t4[0]; bh[2 * p][1] = t4[1];
                    bh[2 * p + 1][0] = t4[2]; bh[2 * p + 1][1] = t4[3];
                }
#pragma unroll
                for (int mt = 0; mt < 2; mt++)
#pragma unroll
                    for (int nt = 0; nt < 4; nt++)
                        mma_f16(acc[mt][nt], a[mt], bh[nt][0], bh[nt][1]);
            }
        }

        mbar_wait(mb_ea, k & 1);
#pragma unroll
        for (int ks = 0; ks < 2; ks++) {
            uint32_t a[2][4];
#pragma unroll
            for (int mt = 0; mt < 2; mt++) {
                int r = m0 + mt * 16 + (gA_r << 3) + gi;
                ldsm_x4(a[mt], smb + ESM_EA + (uint32_t)(r * 64 + (ks * 2 + gA_c) * 16));
            }
            uint32_t bh[4][2];
#pragma unroll
            for (int p = 0; p < 2; p++) {
                int n = n0 + (p << 4) + (gB_r << 3) + gi;
                uint32_t t4[4];
                ldsm_x4(t4, smb + ESM_B4 + (uint32_t)(n * 64 + (ks * 2 + gB_c) * 16));
                bh[2 * p][0] = t4[0]; bh[2 * p][1] = t4[1];
                bh[2 * p + 1][0] = t4[2]; bh[2 * p + 1][1] = t4[3];
            }
#pragma unroll
            for (int mt = 0; mt < 2; mt++)
#pragma unroll
                for (int nt = 0; nt < 4; nt++)
                    mma_f16(acc[mt][nt], a[mt], bh[nt][0], bh[nt][1]);
        }

        {
            float p[4][4];
#pragma unroll
            for (int i = 0; i < 4; i++)
#pragma unroll
                for (int j = 0; j < 4; j++) p[i][j] = 0.f;

#pragma unroll
            for (int mt = 0; mt < 2; mt++)
#pragma unroll
                for (int hf = 0; hf < 2; hf++) {
                    int ri = mt * 2 + hf;
#pragma unroll
                    for (int nt = 0; nt < 4; nt++)
#pragma unroll
                        for (int e = 0; e < 2; e++) {
                            int colg = n0 + nt * 8 + (lane & 3) * 2 + e;
                            float h1 = fmaxf(acc[mt][nt][hf * 2 + e] + b1s[colg], 0.f);
#pragma unroll
                            for (int cc = 0; cc < 4; cc++)
                                p[ri][cc] += h1 * w2s[colg * 4 + cc];
                        }
                }
#pragma unroll
            for (int i = 0; i < 4; i++)
#pragma unroll
                for (int cc = 0; cc < 4; cc++) {
                    p[i][cc] += __shfl_xor_sync(0xffffffffu, p[i][cc], 1);
                    p[i][cc] += __shfl_xor_sync(0xffffffffu, p[i][cc], 2);
                }
            if ((lane & 3) == 0) {
#pragma unroll
                for (int mt = 0; mt < 2; mt++)
#pragma unroll
                    for (int hf = 0; hf < 2; hf++) {
                        int r = m0 + mt * 16 + (lane >> 2) + hf * 8;
#pragma unroll
                        for (int cc = 0; cc < 4; cc++)
                            opart[wn * 512 + r * 4 + cc] = p[mt * 2 + hf][cc];
                    }
            }
            __syncthreads();
            {
                int r = tid >> 2, cc = tid & 3;
                float s = opart[tid] + opart[512 + tid] + opart[1024 + tid]
                        + opart[1536 + tid] + b2s[cc];
                if (e0 + r < EE) out[(size_t)(e0 + r) * 4 + cc] = s;
            }
            __syncthreads();
        }

        if (k + 2 < nLocal) fill_st(k + 2);
        if (k + 1 < nLocal) fill_ea(k + 1);
    }
}

// ---------------------------------------------------------------------------
extern "C" void kernel_launch(void* const* d_in, const int* in_sizes, int n_in,
                              void* d_out, int out_size)
{
    const float* x   = (const float*)d_in[0];
    const int*   ei  = (const int*)  d_in[1];
    const float* ea  = (const float*)d_in[2];
    const float* We  = (const float*)d_in[3];
    const float* be  = (const float*)d_in[4];
    const float* Wc1 = (const float*)d_in[5];
    const float* bc1 = (const float*)d_in[6];
    const float* Wc2 = (const float*)d_in[7];
    const float* bc2 = (const float*)d_in[8];
    const float* Wn1 = (const float*)d_in[9];
    const float* bn1 = (const float*)d_in[10];
    const float* Wn2 = (const float*)d_in[11];
    const float* bn2 = (const float*)d_in[12];
    const float* We1 = (const float*)d_in[13];
    const float* be1 = (const float*)d_in[14];
    const float* We2 = (const float*)d_in[15];
    const float* be2 = (const float*)d_in[16];

    const int* row = ei;
    const int* col = ei + EE;

    float* out_node = (float*)d_out;
    float* out_edge = out_node + (size_t)NN * CN;

    float *pxw, *pdinv;
    int *pdeg, *ppart, *prs, *pcur, *pbsum, *pboff, *pcsr;
    __half *pxh, *pxl, *phh, *phl, *pea16, *pw1h;
    __half *wWeH, *wWeL, *wC1H, *wC1L, *wC2H, *wC2L, *wN1H, *wN1L;
    cudaGetSymbolAddress((void**)&pxw,   g_xw);
    cudaGetSymbolAddress((void**)&pdinv, g_dinv);
    cudaGetSymbolAddress((void**)&pdeg,  g_deg);
    cudaGetSymbolAddress((void**)&ppart, g_part);
    cudaGetSymbolAddress((void**)&prs,   g_rs);
    cudaGetSymbolAddress((void**)&pcur,  g_cur);
    cudaGetSymbolAddress((void**)&pbsum, g_blksum);
    cudaGetSymbolAddress((void**)&pboff, g_blkoff);
    cudaGetSymbolAddress((void**)&pcsr,  g_csr);
    cudaGetSymbolAddress((void**)&pxh,   g_xh);
    cudaGetSymbolAddress((void**)&pxl,   g_xl);
    cudaGetSymbolAddress((void**)&phh,   g_hh);
    cudaGetSymbolAddress((void**)&phl,   g_hl);
    cudaGetSymbolAddress((void**)&pea16, g_ea16);
    cudaGetSymbolAddress((void**)&pw1h,  g_w1h);
    cudaGetSymbolAddress((void**)&wWeH,  g_wWe_h);
    cudaGetSymbolAddress((void**)&wWeL,  g_wWe_l);
    cudaGetSymbolAddress((void**)&wC1H,  g_wC1_h);
    cudaGetSymbolAddress((void**)&wC1L,  g_wC1_l);
    cudaGetSymbolAddress((void**)&wC2H,  g_wC2_h);
    cudaGetSymbolAddress((void**)&wC2L,  g_wC2_l);
    cudaGetSymbolAddress((void**)&wN1H,  g_wN1_h);
    cudaGetSymbolAddress((void**)&wN1L,  g_wN1_l);

    static bool init_done = false;
    static cudaStream_t sB;
    static cudaEvent_t ev0, evB, evH, evE;
    if (!init_done) {
        cudaFuncSetAttribute(k_edge, cudaFuncAttributeMaxDynamicSharedMemorySize, ESM_END);
        cudaFuncSetAttribute(k_mm<1,0>, cudaFuncAttributeMaxDynamicSharedMemorySize, MM_SM_END);
        cudaFuncSetAttribute(k_mm<2,1>, cudaFuncAttributeMaxDynamicSharedMemorySize, MM_SM_END);
        cudaFuncSetAttribute(k_mm<2,5>, cudaFuncAttributeMaxDynamicSharedMemorySize, MM_SM_END);
        cudaStreamCreateWithFlags(&sB, cudaStreamNonBlocking);
        cudaEventCreateWithFlags(&ev0, cudaEventDisableTiming);
        cudaEventCreateWithFlags(&evB, cudaEventDisableTiming);
        cudaEventCreateWithFlags(&evH, cudaEventDisableTiming);
        cudaEventCreateWithFlags(&evE, cudaEventDisableTiming);
        init_done = true;
    }

    const int T = 256;

    // fork: streamB handles CSR build + edge-side conversions
    cudaEventRecord(ev0, 0);
    cudaStreamWaitEvent(sB, ev0, 0);

    k_deg_init<<<(NN + T - 1) / T, T, 0, sB>>>(pdeg);
    k_deg_edges<<<(EE + T - 1) / T, T, 0, sB>>>(col, pdeg);
    k_dinv<<<(NN + T - 1) / T, T, 0, sB>>>(pdeg, pdinv);
    k_scan1<<<NBLK, 256, 0, sB>>>(pdeg, ppart, pbsum);
    k_scan2<<<1, 256, 0, sB>>>(pbsum, pboff);
    k_scan3<<<NBLK, 256, 0, sB>>>(ppart, pboff, prs, pcur);
    k_fill<<<(EE + T - 1) / T, T, 0, sB>>>(row, col, pcur, pcsr);
    {
        size_t n8 = (size_t)EE * FE / 8;
        k_tof16_v<<<(int)((n8 + T - 1) / T), T, 0, sB>>>((const float4*)ea,
                                                         (uint4*)pea16, n8);
    }
    k_w1t16<<<(HH * KTOT + T - 1) / T, T, 0, sB>>>(We1, pw1h);
    cudaEventRecord(evB, sB);

    // main stream: splits + embed + conv1 (overlaps with streamB)
    k_splitA<<<(int)(((size_t)NN * FN + T - 1) / T), T>>>(x, pxh, pxl, (size_t)NN * FN);
    k_splitWt<<<(128 * 64 + T - 1) / T, T>>>(We, wWeH, wWeL, 64, 128);
    k_splitWt<<<(128 * 128 + T - 1) / T, T>>>(Wc1, wC1H, wC1L, 128, 128);
    k_splitWt<<<(128 * 128 + T - 1) / T, T>>>(Wc2, wC2H, wC2L, 128, 128);
    k_splitWt<<<(128 * 128 + T - 1) / T, T>>>(Wn1, wN1H, wN1L, 128, 64);

    k_mm<1,0><<<GRID_P, 512, MM_SM_END>>>(pxh, pxl, wWeH, wWeL, be,
                                          nullptr, phh, phl, nullptr, nullptr, NN, 128);
    k_mm<2,1><<<GRID_P, 512, MM_SM_END>>>(phh, phl, wC1H, wC1L, nullptr,
                                          pxw, nullptr, nullptr, nullptr, nullptr, NN, 128);

    // join: pull needs CSR from streamB
    cudaStreamWaitEvent(0, evB, 0);
    k_pull<<<(NN * 32 + T - 1) / T, T>>>(pxw, pcsr, prs, pdeg, pdinv, bc1, phh, phl);

    k_mm<2,1><<<GRID_P, 512, MM_SM_END>>>(phh, phl, wC2H, wC2L, nullptr,
                                          pxw, nullptr, nullptr, nullptr, nullptr, NN, 128);
    k_pull<<<(NN * 32 + T - 1) / T, T>>>(pxw, pcsr, prs, pdeg, pdinv, bc2, phh, phl);

    // fork: k_edge on streamB concurrent with node head on main
    cudaEventRecord(evH, 0);
    cudaStreamWaitEvent(sB, evH, 0);
    k_edge<<<GRID_P, 512, ESM_END, sB>>>(phh, pea16, pw1h, row, col,
                                         be1, We2, be2, out_edge);
    cudaEventRecord(evE, sB);

    k_mm<2,5><<<GRID_P, 512, MM_SM_END>>>(phh, phl, wN1H, wN1L, bn1,
                                          out_node, nullptr, nullptr, Wn2, bn2, NN, 64);

    // join k_edge back into the main stream before returning
    cudaStreamWaitEvent(0, evE, 0);
}